// round 1
// baseline (speedup 1.0000x reference)
#include <cuda_runtime.h>

// Problem constants (fixed shapes from the reference)
#define BATCH   8
#define CH      8
#define NPIX    262144            // 512*512
#define KSEG    17
#define NG      (NPIX/4)          // float4 / int4 groups per batch = 65536
#define BLOCKS_X 128
#define THREADS  256
#define WARPS    (THREADS/32)

#define DELTA_V 0.5f
#define TWO_DELTA_D 3.0f
#define EPSV 1e-12f

// Scratch (device globals; no dynamic allocation allowed)
__device__ float  g_sums[BATCH*KSEG*CH];
__device__ float  g_counts[BATCH*KSEG];
__device__ float  g_pen[BATCH*KSEG];
__device__ uchar4 g_seg[BATCH*NG];

// ---------------------------------------------------------------------------
__global__ void k_zero() {
    int i = blockIdx.x * blockDim.x + threadIdx.x;
    if (i < BATCH*KSEG*CH) g_sums[i] = 0.f;
    if (i < BATCH*KSEG) { g_counts[i] = 0.f; g_pen[i] = 0.f; }
}

// ---------------------------------------------------------------------------
// Pass 1: per-(batch,segment) channel sums + counts. Also caches seg id (u8).
// Segment 0 (background / masked-out) never contributes to the loss -> skip.
__global__ __launch_bounds__(THREADS)
void k_accum(const float4* __restrict__ emb,
             const int4*   __restrict__ lab,
             const int4*   __restrict__ msk) {
    const int b    = blockIdx.y;
    const int tid  = threadIdx.x;
    const int warp = tid >> 5;

    __shared__ float acc[WARPS][KSEG*9];   // [warp][seg][c0..c7, count]
    float* accf = &acc[0][0];
    for (int i = tid; i < WARPS*KSEG*9; i += THREADS) accf[i] = 0.f;
    __syncthreads();

    float* wa = acc[warp];

    const int per_block = NG / BLOCKS_X;   // 512
    const int base = blockIdx.x * per_block;
    const float4* embb = emb + (size_t)b * CH * NG;
    const int4*   labb = lab + (size_t)b * NG;
    const int4*   mskb = msk + (size_t)b * NG;
    uchar4*       segb = g_seg + (size_t)b * NG;

    for (int g = base + tid; g < base + per_block; g += THREADS) {
        int4 l = labb[g];
        int4 m = mskb[g];
        int s0 = m.x ? l.x : 0;
        int s1 = m.y ? l.y : 0;
        int s2 = m.z ? l.z : 0;
        int s3 = m.w ? l.w : 0;
        segb[g] = make_uchar4((unsigned char)s0, (unsigned char)s1,
                              (unsigned char)s2, (unsigned char)s3);
        if ((s0 | s1 | s2 | s3) == 0) continue;

        float4 e[CH];
        #pragma unroll
        for (int c = 0; c < CH; c++) e[c] = embb[(size_t)c * NG + g];

        if (s0) {
            float* a = &wa[s0*9];
            #pragma unroll
            for (int c = 0; c < CH; c++) atomicAdd(&a[c], e[c].x);
            atomicAdd(&a[8], 1.f);
        }
        if (s1) {
            float* a = &wa[s1*9];
            #pragma unroll
            for (int c = 0; c < CH; c++) atomicAdd(&a[c], e[c].y);
            atomicAdd(&a[8], 1.f);
        }
        if (s2) {
            float* a = &wa[s2*9];
            #pragma unroll
            for (int c = 0; c < CH; c++) atomicAdd(&a[c], e[c].z);
            atomicAdd(&a[8], 1.f);
        }
        if (s3) {
            float* a = &wa[s3*9];
            #pragma unroll
            for (int c = 0; c < CH; c++) atomicAdd(&a[c], e[c].w);
            atomicAdd(&a[8], 1.f);
        }
    }
    __syncthreads();

    // Reduce warp copies, flush to global
    for (int i = tid; i < KSEG*9; i += THREADS) {
        float v = 0.f;
        #pragma unroll
        for (int w = 0; w < WARPS; w++) v += acc[w][i];
        int s = i / 9, r = i - s*9;
        if (s != 0 && v != 0.f) {
            if (r < 8) atomicAdd(&g_sums[(b*KSEG + s)*CH + r], v);
            else       atomicAdd(&g_counts[b*KSEG + s], v);
        }
    }
}

// ---------------------------------------------------------------------------
// Pass 2: hinged pull penalty per pixel, accumulated per (batch,segment).
__global__ __launch_bounds__(THREADS)
void k_pen(const float4* __restrict__ emb) {
    const int b    = blockIdx.y;
    const int tid  = threadIdx.x;
    const int warp = tid >> 5;

    __shared__ float smean[KSEG*CH];
    __shared__ float spen[WARPS][KSEG];

    for (int i = tid; i < KSEG*CH; i += THREADS) {
        int s = i / CH, c = i - s*CH;
        smean[i] = g_sums[(b*KSEG + s)*CH + c] / fmaxf(g_counts[b*KSEG + s], 1.f);
    }
    for (int i = tid; i < WARPS*KSEG; i += THREADS) (&spen[0][0])[i] = 0.f;
    __syncthreads();

    float* wp = spen[warp];

    const int per_block = NG / BLOCKS_X;
    const int base = blockIdx.x * per_block;
    const float4* embb = emb + (size_t)b * CH * NG;
    const uchar4* segb = g_seg + (size_t)b * NG;

    for (int g = base + tid; g < base + per_block; g += THREADS) {
        uchar4 s4 = segb[g];
        if ((s4.x | s4.y | s4.z | s4.w) == 0) continue;

        float4 e[CH];
        #pragma unroll
        for (int c = 0; c < CH; c++) e[c] = embb[(size_t)c * NG + g];

        if (s4.x) {
            float ss = 0.f;
            #pragma unroll
            for (int c = 0; c < CH; c++) { float d = e[c].x - smean[s4.x*CH + c]; ss = fmaf(d, d, ss); }
            float d = sqrtf(fmaxf(ss, EPSV));
            float h = fmaxf(d - DELTA_V, 0.f);
            atomicAdd(&wp[s4.x], h*h);
        }
        if (s4.y) {
            float ss = 0.f;
            #pragma unroll
            for (int c = 0; c < CH; c++) { float d = e[c].y - smean[s4.y*CH + c]; ss = fmaf(d, d, ss); }
            float d = sqrtf(fmaxf(ss, EPSV));
            float h = fmaxf(d - DELTA_V, 0.f);
            atomicAdd(&wp[s4.y], h*h);
        }
        if (s4.z) {
            float ss = 0.f;
            #pragma unroll
            for (int c = 0; c < CH; c++) { float d = e[c].z - smean[s4.z*CH + c]; ss = fmaf(d, d, ss); }
            float d = sqrtf(fmaxf(ss, EPSV));
            float h = fmaxf(d - DELTA_V, 0.f);
            atomicAdd(&wp[s4.z], h*h);
        }
        if (s4.w) {
            float ss = 0.f;
            #pragma unroll
            for (int c = 0; c < CH; c++) { float d = e[c].w - smean[s4.w*CH + c]; ss = fmaf(d, d, ss); }
            float d = sqrtf(fmaxf(ss, EPSV));
            float h = fmaxf(d - DELTA_V, 0.f);
            atomicAdd(&wp[s4.w], h*h);
        }
    }
    __syncthreads();

    for (int i = tid; i < KSEG; i += THREADS) {
        float v = 0.f;
        #pragma unroll
        for (int w = 0; w < WARPS; w++) v += spen[w][i];
        if (i != 0 && v != 0.f) atomicAdd(&g_pen[b*KSEG + i], v);
    }
}

// ---------------------------------------------------------------------------
// Finalize: pull_b / push_b / valid reduction over batches, write 2 scalars.
__global__ void k_final(float* __restrict__ out, int out_size) {
    __shared__ float pull[BATCH], push[BATCH], valid[BATCH];
    int t = threadIdx.x;
    if (t < BATCH) {
        int b = t;
        float cnt[KSEG];
        float Kc = 0.f, pullsum = 0.f;
        cnt[0] = 0.f;
        for (int s = 1; s < KSEG; s++) {
            cnt[s] = g_counts[b*KSEG + s];
            if (cnt[s] > 0.f) {
                Kc += 1.f;
                pullsum += g_pen[b*KSEG + s] / cnt[s];
            }
        }
        pull[b] = pullsum / fmaxf(Kc, 1.f);

        float hs = 0.f, np = 0.f;
        for (int i = 1; i < KSEG; i++) {
            if (cnt[i] <= 0.f) continue;
            float mi[CH];
            #pragma unroll
            for (int c = 0; c < CH; c++) mi[c] = g_sums[(b*KSEG + i)*CH + c] / cnt[i];
            for (int j = i + 1; j < KSEG; j++) {
                if (cnt[j] <= 0.f) continue;
                float ss = 0.f;
                #pragma unroll
                for (int c = 0; c < CH; c++) {
                    float dm = mi[c] - g_sums[(b*KSEG + j)*CH + c] / cnt[j];
                    ss = fmaf(dm, dm, ss);
                }
                float dist = sqrtf(fmaxf(ss, EPSV));
                float hg = fmaxf(TWO_DELTA_D - dist, 0.f);
                hs += hg*hg;
                np += 1.f;
            }
        }
        push[b]  = hs / fmaxf(np, 1.f);
        valid[b] = (Kc > 0.f) ? 1.f : 0.f;
    }
    __syncthreads();
    if (t == 0) {
        float nv = 0.f, sp = 0.f, sh = 0.f;
        for (int b = 0; b < BATCH; b++) {
            nv += valid[b];
            sp += pull[b] * valid[b];
            sh += push[b] * valid[b];
        }
        nv = fmaxf(nv, 1.f);
        out[0] = sp / nv;
        if (out_size > 1) out[1] = sh / nv;
    }
}

// ---------------------------------------------------------------------------
extern "C" void kernel_launch(void* const* d_in, const int* in_sizes, int n_in,
                              void* d_out, int out_size) {
    const float4* emb = (const float4*)d_in[0];
    const int4*   lab = (const int4*)d_in[1];
    const int4*   msk = (const int4*)d_in[2];
    float* out = (float*)d_out;

    k_zero<<<(BATCH*KSEG*CH + THREADS - 1)/THREADS, THREADS>>>();
    dim3 grid(BLOCKS_X, BATCH);
    k_accum<<<grid, THREADS>>>(emb, lab, msk);
    k_pen<<<grid, THREADS>>>(emb);
    k_final<<<1, 32>>>(out, out_size);
}

// round 2
// speedup vs baseline: 1.4464x; 1.4464x over previous
#include <cuda_runtime.h>

// Problem constants (fixed shapes from the reference)
#define BATCH   8
#define CH      8
#define NPIX    262144            // 512*512
#define KSEG    17
#define NG      (NPIX/4)          // float4 / int4 groups per batch = 65536
#define BLOCKS_X 128
#define THREADS  256
#define WARPS    (THREADS/32)

#define DELTA_V 0.5f
#define TWO_DELTA_D 3.0f
#define EPSV 1e-12f

// Scratch (device globals; no dynamic allocation allowed)
__device__ float  g_sums[BATCH*KSEG*CH];
__device__ float  g_counts[BATCH*KSEG];
__device__ float  g_pen[BATCH*KSEG];
__device__ uchar4 g_seg[BATCH*NG];

// ---------------------------------------------------------------------------
__global__ void k_zero() {
    int i = blockIdx.x * blockDim.x + threadIdx.x;
    if (i < BATCH*KSEG*CH) g_sums[i] = 0.f;
    if (i < BATCH*KSEG) { g_counts[i] = 0.f; g_pen[i] = 0.f; }
}

// ---------------------------------------------------------------------------
// Pass 1: per-(batch,segment) channel sums + counts. Also caches seg id (u8).
// Segment 0 (background / masked-out) never contributes to the loss -> skip.
__global__ __launch_bounds__(THREADS)
void k_accum(const float4* __restrict__ emb,
             const int4*   __restrict__ lab,
             const int4*   __restrict__ msk) {
    const int b    = blockIdx.y;
    const int tid  = threadIdx.x;
    const int warp = tid >> 5;

    __shared__ float acc[WARPS][KSEG*9];   // [warp][seg][c0..c7, count]
    float* accf = &acc[0][0];
    for (int i = tid; i < WARPS*KSEG*9; i += THREADS) accf[i] = 0.f;
    __syncthreads();

    float* wa = acc[warp];

    const int per_block = NG / BLOCKS_X;   // 512
    const int base = blockIdx.x * per_block;
    const float4* embb = emb + (size_t)b * CH * NG;
    const int4*   labb = lab + (size_t)b * NG;
    const int4*   mskb = msk + (size_t)b * NG;
    uchar4*       segb = g_seg + (size_t)b * NG;

    for (int g = base + tid; g < base + per_block; g += THREADS) {
        int4 l = labb[g];
        int4 m = mskb[g];
        int s0 = m.x ? l.x : 0;
        int s1 = m.y ? l.y : 0;
        int s2 = m.z ? l.z : 0;
        int s3 = m.w ? l.w : 0;
        segb[g] = make_uchar4((unsigned char)s0, (unsigned char)s1,
                              (unsigned char)s2, (unsigned char)s3);
        if ((s0 | s1 | s2 | s3) == 0) continue;

        float4 e[CH];
        #pragma unroll
        for (int c = 0; c < CH; c++) e[c] = embb[(size_t)c * NG + g];

        if (s0) {
            float* a = &wa[s0*9];
            #pragma unroll
            for (int c = 0; c < CH; c++) atomicAdd(&a[c], e[c].x);
            atomicAdd(&a[8], 1.f);
        }
        if (s1) {
            float* a = &wa[s1*9];
            #pragma unroll
            for (int c = 0; c < CH; c++) atomicAdd(&a[c], e[c].y);
            atomicAdd(&a[8], 1.f);
        }
        if (s2) {
            float* a = &wa[s2*9];
            #pragma unroll
            for (int c = 0; c < CH; c++) atomicAdd(&a[c], e[c].z);
            atomicAdd(&a[8], 1.f);
        }
        if (s3) {
            float* a = &wa[s3*9];
            #pragma unroll
            for (int c = 0; c < CH; c++) atomicAdd(&a[c], e[c].w);
            atomicAdd(&a[8], 1.f);
        }
    }
    __syncthreads();

    // Reduce warp copies, flush to global
    for (int i = tid; i < KSEG*9; i += THREADS) {
        float v = 0.f;
        #pragma unroll
        for (int w = 0; w < WARPS; w++) v += acc[w][i];
        int s = i / 9, r = i - s*9;
        if (s != 0 && v != 0.f) {
            if (r < 8) atomicAdd(&g_sums[(b*KSEG + s)*CH + r], v);
            else       atomicAdd(&g_counts[b*KSEG + s], v);
        }
    }
}

// ---------------------------------------------------------------------------
// Pass 2: hinged pull penalty per pixel, accumulated per (batch,segment).
__global__ __launch_bounds__(THREADS)
void k_pen(const float4* __restrict__ emb) {
    const int b    = blockIdx.y;
    const int tid  = threadIdx.x;
    const int warp = tid >> 5;

    __shared__ float smean[KSEG*CH];
    __shared__ float spen[WARPS][KSEG];

    for (int i = tid; i < KSEG*CH; i += THREADS) {
        int s = i / CH, c = i - s*CH;
        smean[i] = g_sums[(b*KSEG + s)*CH + c] / fmaxf(g_counts[b*KSEG + s], 1.f);
    }
    for (int i = tid; i < WARPS*KSEG; i += THREADS) (&spen[0][0])[i] = 0.f;
    __syncthreads();

    float* wp = spen[warp];

    const int per_block = NG / BLOCKS_X;
    const int base = blockIdx.x * per_block;
    const float4* embb = emb + (size_t)b * CH * NG;
    const uchar4* segb = g_seg + (size_t)b * NG;

    for (int g = base + tid; g < base + per_block; g += THREADS) {
        uchar4 s4 = segb[g];
        if ((s4.x | s4.y | s4.z | s4.w) == 0) continue;

        float4 e[CH];
        #pragma unroll
        for (int c = 0; c < CH; c++) e[c] = embb[(size_t)c * NG + g];

        if (s4.x) {
            float ss = 0.f;
            #pragma unroll
            for (int c = 0; c < CH; c++) { float d = e[c].x - smean[s4.x*CH + c]; ss = fmaf(d, d, ss); }
            float d = sqrtf(fmaxf(ss, EPSV));
            float h = fmaxf(d - DELTA_V, 0.f);
            atomicAdd(&wp[s4.x], h*h);
        }
        if (s4.y) {
            float ss = 0.f;
            #pragma unroll
            for (int c = 0; c < CH; c++) { float d = e[c].y - smean[s4.y*CH + c]; ss = fmaf(d, d, ss); }
            float d = sqrtf(fmaxf(ss, EPSV));
            float h = fmaxf(d - DELTA_V, 0.f);
            atomicAdd(&wp[s4.y], h*h);
        }
        if (s4.z) {
            float ss = 0.f;
            #pragma unroll
            for (int c = 0; c < CH; c++) { float d = e[c].z - smean[s4.z*CH + c]; ss = fmaf(d, d, ss); }
            float d = sqrtf(fmaxf(ss, EPSV));
            float h = fmaxf(d - DELTA_V, 0.f);
            atomicAdd(&wp[s4.z], h*h);
        }
        if (s4.w) {
            float ss = 0.f;
            #pragma unroll
            for (int c = 0; c < CH; c++) { float d = e[c].w - smean[s4.w*CH + c]; ss = fmaf(d, d, ss); }
            float d = sqrtf(fmaxf(ss, EPSV));
            float h = fmaxf(d - DELTA_V, 0.f);
            atomicAdd(&wp[s4.w], h*h);
        }
    }
    __syncthreads();

    for (int i = tid; i < KSEG; i += THREADS) {
        float v = 0.f;
        #pragma unroll
        for (int w = 0; w < WARPS; w++) v += spen[w][i];
        if (i != 0 && v != 0.f) atomicAdd(&g_pen[b*KSEG + i], v);
    }
}

// ---------------------------------------------------------------------------
// Finalize: fully parallel in-block version.
// Stage all scratch into smem (coalesced), compute means/pull/push in parallel,
// combine with one thread. Replaces the 72us latency-serialized version.
#define NPAIR 120   // C(16,2) pairs among segments 1..16
__global__ __launch_bounds__(256)
void k_final(float* __restrict__ out, int out_size) {
    __shared__ float s_sum [BATCH*KSEG*CH];   // 1088
    __shared__ float s_cnt [BATCH*KSEG];      // 136
    __shared__ float s_pen [BATCH*KSEG];      // 136
    __shared__ float s_mean[BATCH*KSEG*CH];   // 1088
    __shared__ float s_pull[BATCH], s_K[BATCH], s_push[BATCH], s_np[BATCH];

    const int t = threadIdx.x;

    for (int i = t; i < BATCH*KSEG*CH; i += 256) s_sum[i] = g_sums[i];
    for (int i = t; i < BATCH*KSEG;    i += 256) { s_cnt[i] = g_counts[i]; s_pen[i] = g_pen[i]; }
    if (t < BATCH) { s_pull[t] = 0.f; s_K[t] = 0.f; s_push[t] = 0.f; s_np[t] = 0.f; }
    __syncthreads();

    // means
    for (int i = t; i < BATCH*KSEG*CH; i += 256) {
        int bs = i / CH;
        s_mean[i] = s_sum[i] / fmaxf(s_cnt[bs], 1.f);
    }
    __syncthreads();

    // pull: one thread per (b, s)
    for (int i = t; i < BATCH*KSEG; i += 256) {
        int s = i % KSEG;
        if (s != 0 && s_cnt[i] > 0.f) {
            int b = i / KSEG;
            atomicAdd(&s_pull[b], s_pen[i] / s_cnt[i]);
            atomicAdd(&s_K[b], 1.f);
        }
    }

    // push: one thread per (b, pair), 8*120 = 960 work items
    for (int pg = t; pg < BATCH*NPAIR; pg += 256) {
        int b = pg / NPAIR;
        int p = pg % NPAIR;
        // triangular decode: i in 1..15, j in i+1..16
        int i = 1, rem = p, row = 15;
        while (rem >= row) { rem -= row; i++; row--; }
        int j = i + 1 + rem;

        if (s_cnt[b*KSEG + i] > 0.f && s_cnt[b*KSEG + j] > 0.f) {
            const float* mi = &s_mean[(b*KSEG + i)*CH];
            const float* mj = &s_mean[(b*KSEG + j)*CH];
            float ss = 0.f;
            #pragma unroll
            for (int c = 0; c < CH; c++) { float dm = mi[c] - mj[c]; ss = fmaf(dm, dm, ss); }
            float dist = sqrtf(fmaxf(ss, EPSV));
            float hg = fmaxf(TWO_DELTA_D - dist, 0.f);
            atomicAdd(&s_push[b], hg*hg);
            atomicAdd(&s_np[b], 1.f);
        }
    }
    __syncthreads();

    if (t == 0) {
        float nv = 0.f, sp = 0.f, sh = 0.f;
        #pragma unroll
        for (int b = 0; b < BATCH; b++) {
            float K = s_K[b];
            if (K > 0.f) {
                nv += 1.f;
                sp += s_pull[b] / K;
                sh += s_push[b] / fmaxf(s_np[b], 1.f);
            }
        }
        nv = fmaxf(nv, 1.f);
        out[0] = sp / nv;
        if (out_size > 1) out[1] = sh / nv;
    }
}

// ---------------------------------------------------------------------------
extern "C" void kernel_launch(void* const* d_in, const int* in_sizes, int n_in,
                              void* d_out, int out_size) {
    const float4* emb = (const float4*)d_in[0];
    const int4*   lab = (const int4*)d_in[1];
    const int4*   msk = (const int4*)d_in[2];
    float* out = (float*)d_out;

    k_zero<<<(BATCH*KSEG*CH + THREADS - 1)/THREADS, THREADS>>>();
    dim3 grid(BLOCKS_X, BATCH);
    k_accum<<<grid, THREADS>>>(emb, lab, msk);
    k_pen<<<grid, THREADS>>>(emb);
    k_final<<<1, 256>>>(out, out_size);
}